// round 4
// baseline (speedup 1.0000x reference)
#include <cuda_runtime.h>
#include <math.h>

// Problem constants
#define BB 2
#define CC 128
#define HH 64
#define WW 64
#define NH 4
#define DH 32
#define KS 7
#define TOKENS (BB*HH*WW)   // 8192

// Attention tile config
#define TI 8
#define TJ 4
#define NROW 14
#define NCOL 10
#define NPIX (NROW*NCOL) // 140

// Scratch (device globals: no allocation allowed)
__device__ float g_y[TOKENS*CC];
__device__ float g_qkv[TOKENS*3*CC];
__device__ float g_att[TOKENS*CC];

// ---------------------------------------------------------------------------
// NCHW -> NHWC transpose
// ---------------------------------------------------------------------------
__global__ void transpose_in_kernel(const float* __restrict__ x, float* __restrict__ y)
{
    __shared__ float tile[32][33];
    int b   = blockIdx.z;
    int hw0 = blockIdx.x * 32;
    int c0  = blockIdx.y * 32;
    int tx = threadIdx.x, ty = threadIdx.y;
    #pragma unroll
    for (int k = 0; k < 32; k += 8)
        tile[ty + k][tx] = x[((b*CC + c0 + ty + k) * (HH*WW)) + hw0 + tx];
    __syncthreads();
    #pragma unroll
    for (int k = 0; k < 32; k += 8)
        y[(b*(HH*WW) + hw0 + ty + k)*CC + c0 + tx] = tile[tx][ty + k];
}

// ---------------------------------------------------------------------------
// SGEMM v2: C[M,N] = A[M,128] @ W[N,128]^T + bias (opt. q-scale on cols<128)
// BM=BN=64, BK=32, 128 threads, 4x8 per thread, float4 LDS, reg prefetch.
// ---------------------------------------------------------------------------
__global__ __launch_bounds__(128) void gemm_kernel(
    const float* __restrict__ A,
    const float* __restrict__ W,
    const float* __restrict__ bias,
    float* __restrict__ C,
    int N, int scale_q)
{
    __shared__ float As[32][64];   // [k][row]  (transposed in smem)
    __shared__ float Bs[32][64];   // [k][col]

    int m0 = blockIdx.x * 64;
    int n0 = blockIdx.y * 64;
    int tid = threadIdx.x;

    // compute mapping: rows tx*4..+3, cols ty*8..+7
    int tx = tid & 15;
    int ty = tid >> 4;

    // load mapping: float4 column fc (0..7), base row r0 (0..15), 4 row-strides
    int fc = tid & 7;
    int r0 = tid >> 3;

    const float* Ag = A + (m0 + r0)*128 + fc*4;
    const float* Wg = W + (n0 + r0)*128 + fc*4;

    float4 av[4], bv[4];
    #pragma unroll
    for (int s = 0; s < 4; s++) {
        av[s] = *(const float4*)(Ag + s*16*128);
        bv[s] = *(const float4*)(Wg + s*16*128);
    }

    float acc[4][8] = {};

    #pragma unroll
    for (int k0 = 0; k0 < 4; k0++) {
        // stage current tile (transposed)
        #pragma unroll
        for (int s = 0; s < 4; s++) {
            As[fc*4+0][r0 + s*16] = av[s].x;
            As[fc*4+1][r0 + s*16] = av[s].y;
            As[fc*4+2][r0 + s*16] = av[s].z;
            As[fc*4+3][r0 + s*16] = av[s].w;
            Bs[fc*4+0][r0 + s*16] = bv[s].x;
            Bs[fc*4+1][r0 + s*16] = bv[s].y;
            Bs[fc*4+2][r0 + s*16] = bv[s].z;
            Bs[fc*4+3][r0 + s*16] = bv[s].w;
        }
        __syncthreads();

        // prefetch next tile into registers
        if (k0 < 3) {
            #pragma unroll
            for (int s = 0; s < 4; s++) {
                av[s] = *(const float4*)(Ag + (k0+1)*32 + s*16*128);
                bv[s] = *(const float4*)(Wg + (k0+1)*32 + s*16*128);
            }
        }

        #pragma unroll
        for (int kk = 0; kk < 32; kk++) {
            float4 a  = *(const float4*)&As[kk][tx*4];
            float4 b0 = *(const float4*)&Bs[kk][ty*8];
            float4 b1 = *(const float4*)&Bs[kk][ty*8 + 4];
            float ar[4] = {a.x, a.y, a.z, a.w};
            float br[8] = {b0.x, b0.y, b0.z, b0.w, b1.x, b1.y, b1.z, b1.w};
            #pragma unroll
            for (int u = 0; u < 4; u++)
                #pragma unroll
                for (int v = 0; v < 8; v++)
                    acc[u][v] = fmaf(ar[u], br[v], acc[u][v]);
        }
        __syncthreads();
    }

    const float qs = 0.17677669529663687f; // 1/sqrt(32)
    #pragma unroll
    for (int u = 0; u < 4; u++) {
        int row = m0 + tx*4 + u;
        float* crow = C + row*N + n0 + ty*8;
        #pragma unroll
        for (int v = 0; v < 8; v++) {
            int col = n0 + ty*8 + v;
            float val = acc[u][v] + bias[col];
            if (scale_q && col < 128) val *= qs;
            crow[v] = val;
        }
    }
}

// ---------------------------------------------------------------------------
// Neighborhood attention (smem-tiled).
// ---------------------------------------------------------------------------
__global__ __launch_bounds__(256) void attn_kernel(
    const float* __restrict__ qkv,
    const float* __restrict__ rpb,
    float* __restrict__ out)
{
    __shared__ float k_s[NPIX*33];
    __shared__ float v_s[NPIX*32];
    __shared__ float rpb_s[169];

    int j0 = blockIdx.x * TJ;
    int i0 = blockIdx.y * TI;
    int bh = blockIdx.z;
    int b  = bh >> 2;
    int h  = bh & 3;

    int tid  = threadIdx.x;
    int wid  = tid >> 5;
    int lane = tid & 31;

    int rbase = i0 - 3; rbase = rbase < 0 ? 0 : (rbase > HH-NROW ? HH-NROW : rbase);
    int cbase = j0 - 3; cbase = cbase < 0 ? 0 : (cbase > WW-NCOL ? WW-NCOL : cbase);

    for (int r = wid; r < NPIX; r += 8) {
        int gi = r / NCOL, gj = r % NCOL;
        const float* base = qkv + (((b*HH + rbase + gi)*WW) + cbase + gj)*384 + h*DH;
        k_s[r*33 + lane] = base[128 + lane];
        v_s[r*32 + lane] = base[256 + lane];
    }
    if (tid < 169) rpb_s[tid] = rpb[h*169 + tid];
    __syncthreads();

    int i  = i0 + wid;
    int si = i - 3; si = si < 0 ? 0 : (si > HH-KS ? HH-KS : si);
    int rb = si - rbase;
    int di = i - si;

    #pragma unroll
    for (int lj = 0; lj < TJ; lj++) {
        int j  = j0 + lj;
        int sj = j - 3; sj = sj < 0 ? 0 : (sj > WW-KS ? WW-KS : sj);
        int cb = sj - cbase;
        int dj = j - sj;
        int tok = (b*HH + i)*WW + j;

        float q_vec = qkv[tok*384 + h*DH + lane];

        int n0 = lane;
        int n1 = lane + 32; if (n1 > 48) n1 = 48;
        int p0 = n0 / KS, c0 = n0 % KS;
        int p1 = n1 / KS, c1 = n1 % KS;
        const float* k0 = k_s + ((rb + p0)*NCOL + cb + c0)*33;
        const float* k1 = k_s + ((rb + p1)*NCOL + cb + c1)*33;
        float s0 = 0.f, s1 = 0.f;
        #pragma unroll
        for (int d = 0; d < DH; d++) {
            float qd = __shfl_sync(0xffffffffu, q_vec, d);
            s0 = fmaf(qd, k0[d], s0);
            s1 = fmaf(qd, k1[d], s1);
        }
        s0 += rpb_s[(p0 + 6 - di)*13 + (c0 + 6 - dj)];
        s1 += rpb_s[(p1 + 6 - di)*13 + (c1 + 6 - dj)];

        float m = fmaxf(s0, s1);
        #pragma unroll
        for (int o = 16; o > 0; o >>= 1) m = fmaxf(m, __shfl_xor_sync(0xffffffffu, m, o));
        float e0 = __expf(s0 - m);
        float e1 = (lane < 17) ? __expf(s1 - m) : 0.f;
        float se = e0 + e1;
        #pragma unroll
        for (int o = 16; o > 0; o >>= 1) se += __shfl_xor_sync(0xffffffffu, se, o);
        float inv = 1.f / se;
        float w0 = e0 * inv;
        float w1 = e1 * inv;

        float acc = 0.f;
        #pragma unroll
        for (int p = 0; p < KS; p++) {
            const float* vp = v_s + ((rb + p)*NCOL + cb)*32 + lane;
            #pragma unroll
            for (int q = 0; q < KS; q++) {
                int n = p*KS + q;
                float w = (n < 32) ? __shfl_sync(0xffffffffu, w0, n)
                                   : __shfl_sync(0xffffffffu, w1, n - 32);
                acc = fmaf(w, vp[q*32], acc);
            }
        }
        out[tok*CC + h*DH + lane] = acc;
    }
}

// ---------------------------------------------------------------------------
// LayerNorm + NHWC -> NCHW
// ---------------------------------------------------------------------------
__global__ __launch_bounds__(256) void ln_out_kernel(
    const float* __restrict__ y,
    const float* __restrict__ gamma,
    const float* __restrict__ beta,
    float* __restrict__ out)
{
    __shared__ float sh[32][129];
    int tok0 = blockIdx.x * 32;
    int b   = tok0 >> 12;
    int hw0 = tok0 & 4095;
    int w = threadIdx.x >> 5, lane = threadIdx.x & 31;

    #pragma unroll
    for (int t = w*4; t < w*4 + 4; t++) {
        int tok = tok0 + t;
        float v0 = y[tok*CC + lane];
        float v1 = y[tok*CC + lane + 32];
        float v2 = y[tok*CC + lane + 64];
        float v3 = y[tok*CC + lane + 96];
        float s  = v0 + v1 + v2 + v3;
        float s2 = v0*v0 + v1*v1 + v2*v2 + v3*v3;
        #pragma unroll
        for (int o = 16; o > 0; o >>= 1) {
            s  += __shfl_xor_sync(0xffffffffu, s,  o);
            s2 += __shfl_xor_sync(0xffffffffu, s2, o);
        }
        float mu  = s * (1.f/128.f);
        float var = s2 * (1.f/128.f) - mu*mu;
        float rs  = rsqrtf(var + 1e-5f);
        sh[t][lane]      = (v0 - mu)*rs*gamma[lane]      + beta[lane];
        sh[t][lane + 32] = (v1 - mu)*rs*gamma[lane + 32] + beta[lane + 32];
        sh[t][lane + 64] = (v2 - mu)*rs*gamma[lane + 64] + beta[lane + 64];
        sh[t][lane + 96] = (v3 - mu)*rs*gamma[lane + 96] + beta[lane + 96];
    }
    __syncthreads();

    for (int c = w; c < CC; c += 8)
        out[((b*CC + c)*(HH*WW)) + hw0 + lane] = sh[lane][c];
}

// ---------------------------------------------------------------------------
// Launch
// ---------------------------------------------------------------------------
extern "C" void kernel_launch(void* const* d_in, const int* in_sizes, int n_in,
                              void* d_out, int out_size)
{
    const float* x      = (const float*)d_in[0];
    const float* qkv_w  = (const float*)d_in[1];
    const float* qkv_b  = (const float*)d_in[2];
    const float* rpb    = (const float*)d_in[3];
    const float* proj_w = (const float*)d_in[4];
    const float* proj_b = (const float*)d_in[5];
    const float* ln_g   = (const float*)d_in[6];
    const float* ln_b   = (const float*)d_in[7];
    float* out = (float*)d_out;

    float *y, *qkv, *att;
    cudaGetSymbolAddress((void**)&y,   g_y);
    cudaGetSymbolAddress((void**)&qkv, g_qkv);
    cudaGetSymbolAddress((void**)&att, g_att);

    {
        dim3 grid(HH*WW/32, CC/32, BB), block(32, 8);
        transpose_in_kernel<<<grid, block>>>(x, y);
    }

    for (int l = 0; l < 2; l++) {
        {
            dim3 grid(TOKENS/64, 384/64);
            gemm_kernel<<<grid, 128>>>(y, qkv_w + l*384*128, qkv_b + l*384,
                                       qkv, 384, 1);
        }
        {
            dim3 grid(WW/TJ, HH/TI, BB*NH);
            attn_kernel<<<grid, 256>>>(qkv, rpb + l*NH*13*13, att);
        }
        {
            dim3 grid(TOKENS/64, 128/64);
            gemm_kernel<<<grid, 128>>>(att, proj_w + l*128*128, proj_b + l*128,
                                       y, 128, 0);
        }
    }

    ln_out_kernel<<<TOKENS/32, 256>>>(y, ln_g, ln_b, out);
}

// round 5
// speedup vs baseline: 1.6889x; 1.6889x over previous
#include <cuda_runtime.h>
#include <math.h>
#include <stdint.h>

// Problem constants
#define BB 2
#define CC 128
#define HH 64
#define WW 64
#define NH 4
#define DH 32
#define KS 7
#define TOKENS (BB*HH*WW)   // 8192

// Attention tile config
#define TI 8
#define TJ 4
#define NROW 14
#define NCOL 10
#define NPIX (NROW*NCOL) // 140

// Scratch (device globals: no allocation allowed)
__device__ float g_y[TOKENS*CC];
__device__ float g_qkv[TOKENS*3*CC];
__device__ float g_att[TOKENS*CC];

// ---------------------------------------------------------------------------
// NCHW -> NHWC transpose
// ---------------------------------------------------------------------------
__global__ void transpose_in_kernel(const float* __restrict__ x, float* __restrict__ y)
{
    __shared__ float tile[32][33];
    int b   = blockIdx.z;
    int hw0 = blockIdx.x * 32;
    int c0  = blockIdx.y * 32;
    int tx = threadIdx.x, ty = threadIdx.y;
    #pragma unroll
    for (int k = 0; k < 32; k += 8)
        tile[ty + k][tx] = x[((b*CC + c0 + ty + k) * (HH*WW)) + hw0 + tx];
    __syncthreads();
    #pragma unroll
    for (int k = 0; k < 32; k += 8)
        y[(b*(HH*WW) + hw0 + ty + k)*CC + c0 + tx] = tile[tx][ty + k];
}

// ---------------------------------------------------------------------------
// tf32 tensor-core GEMM: C[M,N] = A[M,128] @ W[N,128]^T + bias
// BM=128, BN=64, BK=32, 256 threads = 8 warps (4m x 2n), warp tile 32x32.
// mma.sync.m16n8k8 tf32, fp32 accumulate. Optional q-scale on cols<128.
// ---------------------------------------------------------------------------
__device__ __forceinline__ uint32_t f2tf32(float x)
{
    uint32_t r;
    asm("cvt.rna.tf32.f32 %0, %1;" : "=r"(r) : "f"(x));
    return r;
}

#define SA 36   // smem stride (32 + 4): bank = (4*row + col) % 32, conflict-free frags

__global__ __launch_bounds__(256) void gemm_tc_kernel(
    const float* __restrict__ A,
    const float* __restrict__ W,
    const float* __restrict__ bias,
    float* __restrict__ C,
    int N, int scale_q)
{
    __shared__ float As[128][SA];
    __shared__ float Bs[64][SA];

    int m0 = blockIdx.x * 128;
    int n0 = blockIdx.y * 64;
    int tid  = threadIdx.x;
    int lane = tid & 31;
    int wid  = tid >> 5;
    int wm = wid & 3;        // warp m position (0..3) -> rows wm*32
    int wn = wid >> 2;       // warp n position (0..1) -> cols wn*32
    int gp = lane >> 2;      // group id (0..7)
    int tg = lane & 3;       // thread in group (0..3)

    // global load mapping: row r = tid>>3 (+32*s), float4 col fc = tid&7
    int fc = tid & 7;
    int r0 = tid >> 3;
    const float* Ag = A + (m0 + r0)*128 + fc*4;
    const float* Wg = W + (n0 + r0)*128 + fc*4;

    float4 av[4], bv[2];
    #pragma unroll
    for (int s = 0; s < 4; s++) av[s] = *(const float4*)(Ag + s*32*128);
    #pragma unroll
    for (int s = 0; s < 2; s++) bv[s] = *(const float4*)(Wg + s*32*128);

    float acc[2][4][4];
    #pragma unroll
    for (int mt = 0; mt < 2; mt++)
        #pragma unroll
        for (int nt = 0; nt < 4; nt++)
            #pragma unroll
            for (int c = 0; c < 4; c++) acc[mt][nt][c] = 0.f;

    #pragma unroll
    for (int k0 = 0; k0 < 4; k0++) {
        // stage current chunk
        #pragma unroll
        for (int s = 0; s < 4; s++)
            *(float4*)&As[r0 + s*32][fc*4] = av[s];
        #pragma unroll
        for (int s = 0; s < 2; s++)
            *(float4*)&Bs[r0 + s*32][fc*4] = bv[s];
        __syncthreads();

        // prefetch next chunk
        if (k0 < 3) {
            #pragma unroll
            for (int s = 0; s < 4; s++) av[s] = *(const float4*)(Ag + (k0+1)*32 + s*32*128);
            #pragma unroll
            for (int s = 0; s < 2; s++) bv[s] = *(const float4*)(Wg + (k0+1)*32 + s*32*128);
        }

        #pragma unroll
        for (int ks = 0; ks < 4; ks++) {
            int kb = ks*8;
            uint32_t af[2][4], bf[4][2];
            #pragma unroll
            for (int mt = 0; mt < 2; mt++) {
                int r = wm*32 + mt*16 + gp;
                af[mt][0] = f2tf32(As[r    ][kb + tg    ]);
                af[mt][1] = f2tf32(As[r + 8][kb + tg    ]);
                af[mt][2] = f2tf32(As[r    ][kb + tg + 4]);
                af[mt][3] = f2tf32(As[r + 8][kb + tg + 4]);
            }
            #pragma unroll
            for (int nt = 0; nt < 4; nt++) {
                int c = wn*32 + nt*8 + gp;
                bf[nt][0] = f2tf32(Bs[c][kb + tg    ]);
                bf[nt][1] = f2tf32(Bs[c][kb + tg + 4]);
            }
            #pragma unroll
            for (int mt = 0; mt < 2; mt++)
                #pragma unroll
                for (int nt = 0; nt < 4; nt++) {
                    asm volatile(
                        "mma.sync.aligned.m16n8k8.row.col.f32.tf32.tf32.f32 "
                        "{%0,%1,%2,%3}, {%4,%5,%6,%7}, {%8,%9}, {%0,%1,%2,%3};"
                        : "+f"(acc[mt][nt][0]), "+f"(acc[mt][nt][1]),
                          "+f"(acc[mt][nt][2]), "+f"(acc[mt][nt][3])
                        : "r"(af[mt][0]), "r"(af[mt][1]), "r"(af[mt][2]), "r"(af[mt][3]),
                          "r"(bf[nt][0]), "r"(bf[nt][1]));
                }
        }
        __syncthreads();
    }

    // epilogue: bias + optional q-scale, float2 stores
    const float qs = 0.17677669529663687f; // 1/sqrt(32)
    #pragma unroll
    for (int mt = 0; mt < 2; mt++) {
        int rbase = m0 + wm*32 + mt*16 + gp;
        #pragma unroll
        for (int nt = 0; nt < 4; nt++) {
            int col = n0 + wn*32 + nt*8 + 2*tg;
            float b0 = bias[col], b1 = bias[col + 1];
            float sc = (scale_q && col < 128) ? qs : 1.f;  // q block is 128-aligned
            float2 v0 = make_float2((acc[mt][nt][0] + b0)*sc, (acc[mt][nt][1] + b1)*sc);
            float2 v1 = make_float2((acc[mt][nt][2] + b0)*sc, (acc[mt][nt][3] + b1)*sc);
            *(float2*)&C[rbase*N + col]       = v0;
            *(float2*)&C[(rbase + 8)*N + col] = v1;
        }
    }
}

// ---------------------------------------------------------------------------
// Neighborhood attention (smem-tiled).
// ---------------------------------------------------------------------------
__global__ __launch_bounds__(256) void attn_kernel(
    const float* __restrict__ qkv,
    const float* __restrict__ rpb,
    float* __restrict__ out)
{
    __shared__ float k_s[NPIX*33];
    __shared__ float v_s[NPIX*32];
    __shared__ float rpb_s[169];

    int j0 = blockIdx.x * TJ;
    int i0 = blockIdx.y * TI;
    int bh = blockIdx.z;
    int b  = bh >> 2;
    int h  = bh & 3;

    int tid  = threadIdx.x;
    int wid  = tid >> 5;
    int lane = tid & 31;

    int rbase = i0 - 3; rbase = rbase < 0 ? 0 : (rbase > HH-NROW ? HH-NROW : rbase);
    int cbase = j0 - 3; cbase = cbase < 0 ? 0 : (cbase > WW-NCOL ? WW-NCOL : cbase);

    for (int r = wid; r < NPIX; r += 8) {
        int gi = r / NCOL, gj = r % NCOL;
        const float* base = qkv + (((b*HH + rbase + gi)*WW) + cbase + gj)*384 + h*DH;
        k_s[r*33 + lane] = base[128 + lane];
        v_s[r*32 + lane] = base[256 + lane];
    }
    if (tid < 169) rpb_s[tid] = rpb[h*169 + tid];
    __syncthreads();

    int i  = i0 + wid;
    int si = i - 3; si = si < 0 ? 0 : (si > HH-KS ? HH-KS : si);
    int rb = si - rbase;
    int di = i - si;

    #pragma unroll
    for (int lj = 0; lj < TJ; lj++) {
        int j  = j0 + lj;
        int sj = j - 3; sj = sj < 0 ? 0 : (sj > WW-KS ? WW-KS : sj);
        int cb = sj - cbase;
        int dj = j - sj;
        int tok = (b*HH + i)*WW + j;

        float q_vec = qkv[tok*384 + h*DH + lane];

        int n0 = lane;
        int n1 = lane + 32; if (n1 > 48) n1 = 48;
        int p0 = n0 / KS, c0 = n0 % KS;
        int p1 = n1 / KS, c1 = n1 % KS;
        const float* k0 = k_s + ((rb + p0)*NCOL + cb + c0)*33;
        const float* k1 = k_s + ((rb + p1)*NCOL + cb + c1)*33;
        float s0 = 0.f, s1 = 0.f;
        #pragma unroll
        for (int d = 0; d < DH; d++) {
            float qd = __shfl_sync(0xffffffffu, q_vec, d);
            s0 = fmaf(qd, k0[d], s0);
            s1 = fmaf(qd, k1[d], s1);
        }
        s0 += rpb_s[(p0 + 6 - di)*13 + (c0 + 6 - dj)];
        s1 += rpb_s[(p1 + 6 - di)*13 + (c1 + 6 - dj)];

        float m = fmaxf(s0, s1);
        #pragma unroll
        for (int o = 16; o > 0; o >>= 1) m = fmaxf(m, __shfl_xor_sync(0xffffffffu, m, o));
        float e0 = __expf(s0 - m);
        float e1 = (lane < 17) ? __expf(s1 - m) : 0.f;
        float se = e0 + e1;
        #pragma unroll
        for (int o = 16; o > 0; o >>= 1) se += __shfl_xor_sync(0xffffffffu, se, o);
        float inv = 1.f / se;
        float w0 = e0 * inv;
        float w1 = e1 * inv;

        float acc = 0.f;
        #pragma unroll
        for (int p = 0; p < KS; p++) {
            const float* vp = v_s + ((rb + p)*NCOL + cb)*32 + lane;
            #pragma unroll
            for (int q = 0; q < KS; q++) {
                int n = p*KS + q;
                float w = (n < 32) ? __shfl_sync(0xffffffffu, w0, n)
                                   : __shfl_sync(0xffffffffu, w1, n - 32);
                acc = fmaf(w, vp[q*32], acc);
            }
        }
        out[tok*CC + h*DH + lane] = acc;
    }
}

// ---------------------------------------------------------------------------
// LayerNorm + NHWC -> NCHW
// ---------------------------------------------------------------------------
__global__ __launch_bounds__(256) void ln_out_kernel(
    const float* __restrict__ y,
    const float* __restrict__ gamma,
    const float* __restrict__ beta,
    float* __restrict__ out)
{
    __shared__ float sh[32][129];
    int tok0 = blockIdx.x * 32;
    int b   = tok0 >> 12;
    int hw0 = tok0 & 4095;
    int w = threadIdx.x >> 5, lane = threadIdx.x & 31;

    #pragma unroll
    for (int t = w*4; t < w*4 + 4; t++) {
        int tok = tok0 + t;
        float v0 = y[tok*CC + lane];
        float v1 = y[tok*CC + lane + 32];
        float v2 = y[tok*CC + lane + 64];
        float v3 = y[tok*CC + lane + 96];
        float s  = v0 + v1 + v2 + v3;
        float s2 = v0*v0 + v1*v1 + v2*v2 + v3*v3;
        #pragma unroll
        for (int o = 16; o > 0; o >>= 1) {
            s  += __shfl_xor_sync(0xffffffffu, s,  o);
            s2 += __shfl_xor_sync(0xffffffffu, s2, o);
        }
        float mu  = s * (1.f/128.f);
        float var = s2 * (1.f/128.f) - mu*mu;
        float rs  = rsqrtf(var + 1e-5f);
        sh[t][lane]      = (v0 - mu)*rs*gamma[lane]      + beta[lane];
        sh[t][lane + 32] = (v1 - mu)*rs*gamma[lane + 32] + beta[lane + 32];
        sh[t][lane + 64] = (v2 - mu)*rs*gamma[lane + 64] + beta[lane + 64];
        sh[t][lane + 96] = (v3 - mu)*rs*gamma[lane + 96] + beta[lane + 96];
    }
    __syncthreads();

    for (int c = w; c < CC; c += 8)
        out[((b*CC + c)*(HH*WW)) + hw0 + lane] = sh[lane][c];
}

// ---------------------------------------------------------------------------
// Launch
// ---------------------------------------------------------------------------
extern "C" void kernel_launch(void* const* d_in, const int* in_sizes, int n_in,
                              void* d_out, int out_size)
{
    const float* x      = (const float*)d_in[0];
    const float* qkv_w  = (const float*)d_in[1];
    const float* qkv_b  = (const float*)d_in[2];
    const float* rpb    = (const float*)d_in[3];
    const float* proj_w = (const float*)d_in[4];
    const float* proj_b = (const float*)d_in[5];
    const float* ln_g   = (const float*)d_in[6];
    const float* ln_b   = (const float*)d_in[7];
    float* out = (float*)d_out;

    float *y, *qkv, *att;
    cudaGetSymbolAddress((void**)&y,   g_y);
    cudaGetSymbolAddress((void**)&qkv, g_qkv);
    cudaGetSymbolAddress((void**)&att, g_att);

    {
        dim3 grid(HH*WW/32, CC/32, BB), block(32, 8);
        transpose_in_kernel<<<grid, block>>>(x, y);
    }

    for (int l = 0; l < 2; l++) {
        {
            dim3 grid(TOKENS/128, 384/64);
            gemm_tc_kernel<<<grid, 256>>>(y, qkv_w + l*384*128, qkv_b + l*384,
                                          qkv, 384, 1);
        }
        {
            dim3 grid(WW/TJ, HH/TI, BB*NH);
            attn_kernel<<<grid, 256>>>(qkv, rpb + l*NH*13*13, att);
        }
        {
            dim3 grid(TOKENS/128, 128/64);
            gemm_tc_kernel<<<grid, 256>>>(att, proj_w + l*128*128, proj_b + l*128,
                                          y, 128, 0);
        }
    }

    ln_out_kernel<<<TOKENS/32, 256>>>(y, ln_g, ln_b, out);
}